// round 10
// baseline (speedup 1.0000x reference)
#include <cuda_runtime.h>
#include <cuda_fp16.h>
#include <cstdint>
#include <math.h>

// ============================================================================
// BinaryLinear: y[8192,4096] = x[8192,4096] @ (aa*tanh(kk*W))^T + bias
// fp16 mma.sync.m16n8k16 register GEMM (fp32 acc), ldmatrix.x4, frag dbl-buffer,
// PERSISTENT CTAs: flattened stage counter keeps the cp.async pipeline primed
// across tile boundaries (epilogue overlaps next tile's loads).
// CTA 128x128, 4 warps (2x2), warp tile 64x64, 3-stage, TK=64, 2 CTAs/SM, SW128.
// ============================================================================

#define MDIM 8192
#define NDIM 4096
#define KDIM 4096

#define TM 128
#define TN 128
#define TK 64                          // halves per stage-row (128B)
#define NSTAGES 3
#define KITERS (KDIM / TK)             // 64
#define NTILES ((MDIM / TM) * (NDIM / TN))   // 2048

#define A_STAGE_BYTES (TM * TK * 2)    // 16384
#define B_STAGE_BYTES (TN * TK * 2)    // 16384
#define STAGE_BYTES (A_STAGE_BYTES + B_STAGE_BYTES)     // 32768
#define SMEM_BYTES (NSTAGES * STAGE_BYTES)              // 98304

#define W_PREP_BLOCKS (NDIM * KDIM / 4096)   // 4096 (16 elems/thread)
#define X_PREP_BLOCKS (MDIM * KDIM / 4096)   // 8192

// fp16 operands (persistent scratch)
__device__ __half g_wh[NDIM * KDIM];   // fp16(aa*tanh(kk*W))
__device__ __half g_xh[MDIM * KDIM];   // fp16(x)

// ---------------------------------------------------------------------------
__device__ __forceinline__ uint32_t smem_u32(const void* p) {
    uint32_t a;
    asm("{ .reg .u64 t; cvta.to.shared.u64 t, %1; cvt.u32.u64 %0, t; }" : "=r"(a) : "l"(p));
    return a;
}

__device__ __forceinline__ void cp_async16(uint32_t smem_dst, const void* gmem_src) {
    asm volatile("cp.async.cg.shared.global [%0], [%1], 16;" :: "r"(smem_dst), "l"(gmem_src));
}
#define CP_COMMIT() asm volatile("cp.async.commit_group;" ::: "memory")
#define CP_WAIT(n)  asm volatile("cp.async.wait_group %0;" :: "n"(n) : "memory")

__device__ __forceinline__ void ldmatrix_x4(uint32_t& r0, uint32_t& r1,
                                            uint32_t& r2, uint32_t& r3, uint32_t addr) {
    asm volatile("ldmatrix.sync.aligned.m8n8.x4.shared.b16 {%0,%1,%2,%3}, [%4];"
                 : "=r"(r0), "=r"(r1), "=r"(r2), "=r"(r3) : "r"(addr));
}

__device__ __forceinline__ void mma_f16(float d[4], const uint32_t a[4],
                                        const uint32_t b[2], const float c[4]) {
    asm volatile(
        "mma.sync.aligned.m16n8k16.row.col.f32.f16.f16.f32 "
        "{%0,%1,%2,%3}, {%4,%5,%6,%7}, {%8,%9}, {%10,%11,%12,%13};"
        : "=f"(d[0]), "=f"(d[1]), "=f"(d[2]), "=f"(d[3])
        : "r"(a[0]), "r"(a[1]), "r"(a[2]), "r"(a[3]),
          "r"(b[0]), "r"(b[1]),
          "f"(c[0]), "f"(c[1]), "f"(c[2]), "f"(c[3]));
}

// tile id -> (m0, n0) via grouped swizzle: GROUP_M=8 over 64 m-tiles x 32 n-tiles
__device__ __forceinline__ void tile_coords(int tile, int& m0, int& n0) {
    const int grp = tile >> 8;
    const int rem = tile & 255;
    m0 = ((grp << 3) + (rem & 7)) * TM;
    n0 = (rem >> 3) * TN;
}

// ---------------------------------------------------------------------------
// Fused prep: blocks [0, W_PREP_BLOCKS) convert W (with tanh), the rest X.
// 16 floats -> 16 halves per thread (4 loads, 2 stores; MLP=4).
// ---------------------------------------------------------------------------
__device__ __forceinline__ uint32_t pack2(float lo, float hi) {
    __half2 h = __floats2half2_rn(lo, hi);
    return *reinterpret_cast<uint32_t*>(&h);
}

__global__ void __launch_bounds__(256) prep_all(const float4* __restrict__ w,
                                                const float4* __restrict__ x,
                                                const float* __restrict__ kk,
                                                const float* __restrict__ aa) {
    if (blockIdx.x < W_PREP_BLOCKS) {
        int i = blockIdx.x * 256 + threadIdx.x;
        float k = *kk, a = *aa;
        float4 v0 = w[4 * i], v1 = w[4 * i + 1], v2 = w[4 * i + 2], v3 = w[4 * i + 3];
        uint4 o0, o1;
        o0.x = pack2(a * tanhf(k * v0.x), a * tanhf(k * v0.y));
        o0.y = pack2(a * tanhf(k * v0.z), a * tanhf(k * v0.w));
        o0.z = pack2(a * tanhf(k * v1.x), a * tanhf(k * v1.y));
        o0.w = pack2(a * tanhf(k * v1.z), a * tanhf(k * v1.w));
        o1.x = pack2(a * tanhf(k * v2.x), a * tanhf(k * v2.y));
        o1.y = pack2(a * tanhf(k * v2.z), a * tanhf(k * v2.w));
        o1.z = pack2(a * tanhf(k * v3.x), a * tanhf(k * v3.y));
        o1.w = pack2(a * tanhf(k * v3.z), a * tanhf(k * v3.w));
        reinterpret_cast<uint4*>(g_wh)[2 * i] = o0;
        reinterpret_cast<uint4*>(g_wh)[2 * i + 1] = o1;
    } else {
        int i = (blockIdx.x - W_PREP_BLOCKS) * 256 + threadIdx.x;
        float4 v0 = x[4 * i], v1 = x[4 * i + 1], v2 = x[4 * i + 2], v3 = x[4 * i + 3];
        uint4 o0, o1;
        o0.x = pack2(v0.x, v0.y);  o0.y = pack2(v0.z, v0.w);
        o0.z = pack2(v1.x, v1.y);  o0.w = pack2(v1.z, v1.w);
        o1.x = pack2(v2.x, v2.y);  o1.y = pack2(v2.z, v2.w);
        o1.z = pack2(v3.x, v3.y);  o1.w = pack2(v3.z, v3.w);
        reinterpret_cast<uint4*>(g_xh)[2 * i] = o0;
        reinterpret_cast<uint4*>(g_xh)[2 * i + 1] = o1;
    }
}

// ---------------------------------------------------------------------------
// SMEM: rows of 64 halves (128B = 8 x 16B granules), SW128 swizzle:
// granule c of row r stored at slot (c ^ (r&7)).
// Load global-stage g: tile = bx + (g>>6)*grid, k0 = (g&63)*TK, slot = g%3.
// ---------------------------------------------------------------------------
__device__ __forceinline__ void load_gstage(int g, int bx, int grid,
                                            uint32_t sbase, int tid) {
    int m0, n0;
    tile_coords(bx + (g >> 6) * grid, m0, n0);
    const int k0 = (g & 63) * TK;
    const uint32_t sdst = sbase + (g % NSTAGES) * STAGE_BYTES;
#pragma unroll
    for (int i = 0; i < 8; i++) {                 // A: 1024 granules
        int gg = tid + i * 128;
        int row = gg >> 3, c = gg & 7;
        cp_async16(sdst + row * 128 + ((c ^ (row & 7)) << 4),
                   g_xh + (size_t)(m0 + row) * KDIM + k0 + c * 8);
    }
#pragma unroll
    for (int i = 0; i < 8; i++) {                 // B: 1024 granules
        int gg = tid + i * 128;
        int row = gg >> 3, c = gg & 7;
        cp_async16(sdst + A_STAGE_BYTES + row * 128 + ((c ^ (row & 7)) << 4),
                   g_wh + (size_t)(n0 + row) * KDIM + k0 + c * 8);
    }
}

// ---------------------------------------------------------------------------
// Persistent GEMM: 4 warps (2x2), warp tile 64x64, frag double-buffer.
// ---------------------------------------------------------------------------
__global__ void __launch_bounds__(128, 2) gemm_kernel(const float* __restrict__ bias,
                                                      float* __restrict__ out) {
    extern __shared__ char smem_raw[];
    const uint32_t sbase = smem_u32(smem_raw);

    const int tid = threadIdx.x;
    const int wid = tid >> 5;
    const int lane = tid & 31;
    const int wm = wid >> 1;          // 0..1 -> 64-row slab
    const int wn = wid & 1;           // 0..1 -> 64-col slab
    const int lr = lane >> 2;         // 0..7
    const int lc = lane & 3;          // 0..3

    // ldmatrix lane decomposition
    const int i8 = lane & 7;
    const int sel = lane >> 3;
    const int a_msel = (sel & 1) << 3;
    const int a_gsel = sel >> 1;
    const int b_nsel = (sel >> 1) << 3;
    const int b_gsel = sel & 1;
    const uint32_t aRowOff = (uint32_t)(wm * 64 + a_msel + i8) * 128;
    const uint32_t bRowOff = (uint32_t)(wn * 64 + b_nsel + i8) * 128;

    const int bx = blockIdx.x;
    const int grid = gridDim.x;
    const int my_ntiles = (NTILES - bx + grid - 1) / grid;
    const int total = my_ntiles * KITERS;         // flattened stage count

    float acc[4][8][4];
#pragma unroll
    for (int i = 0; i < 4; i++)
#pragma unroll
        for (int j = 0; j < 8; j++) {
            acc[i][j][0] = 0.f; acc[i][j][1] = 0.f;
            acc[i][j][2] = 0.f; acc[i][j][3] = 0.f;
        }

    // prologue: stages g=0,1 (pipeline stays primed from here on)
#pragma unroll
    for (int g = 0; g < NSTAGES - 1; g++) {
        load_gstage(g, bx, grid, sbase, tid);
        CP_COMMIT();
    }

    uint32_t af[2][4][4];
    uint32_t bf[2][8][2];

    for (int gc = 0; gc < total; ++gc) {
        CP_WAIT(1);              // stage gc resident (one group per iteration)
        __syncthreads();

        const uint32_t aBase = sbase + (gc % NSTAGES) * STAGE_BYTES;
        const uint32_t bBase = aBase + A_STAGE_BYTES;

        // frag load for kq=0 into buffer 0
        {
            const int ga = a_gsel, gb = b_gsel;
#pragma unroll
            for (int ms = 0; ms < 4; ms++)
                ldmatrix_x4(af[0][ms][0], af[0][ms][1], af[0][ms][2], af[0][ms][3],
                            aBase + aRowOff + ms * 2048 + ((ga ^ i8) << 4));
#pragma unroll
            for (int nsp = 0; nsp < 4; nsp++)
                ldmatrix_x4(bf[0][2 * nsp][0], bf[0][2 * nsp][1],
                            bf[0][2 * nsp + 1][0], bf[0][2 * nsp + 1][1],
                            bBase + bRowOff + nsp * 2048 + ((gb ^ i8) << 4));
        }

        // issue loads for stage gc+2 (crosses tile boundaries seamlessly)
        const int gl = gc + NSTAGES - 1;
        if (gl < total)
            load_gstage(gl, bx, grid, sbase, tid);
        CP_COMMIT();             // always commit: CP_WAIT(1) stays valid

#pragma unroll
        for (int kq = 0; kq < 4; kq++) {          // 4 x k16 steps
            const int cur = kq & 1, nxt = cur ^ 1;
            if (kq < 3) {
                const int ga = 2 * (kq + 1) + a_gsel;
                const int gb = 2 * (kq + 1) + b_gsel;
#pragma unroll
                for (int ms = 0; ms < 4; ms++)
                    ldmatrix_x4(af[nxt][ms][0], af[nxt][ms][1],
                                af[nxt][ms][2], af[nxt][ms][3],
                                aBase + aRowOff + ms * 2048 + ((ga ^ i8) << 4));
#pragma unroll
                for (int nsp = 0; nsp < 4; nsp++)
                    ldmatrix_x4(bf[nxt][2 * nsp][0], bf[nxt][2 * nsp][1],
                                bf[nxt][2 * nsp + 1][0], bf[nxt][2 * nsp + 1][1],
                                bBase + bRowOff + nsp * 2048 + ((gb ^ i8) << 4));
            }
#pragma unroll
            for (int ms = 0; ms < 4; ms++)
#pragma unroll
                for (int ns = 0; ns < 8; ns++)
                    mma_f16(acc[ms][ns], af[cur][ms], bf[cur][ns], acc[ms][ns]);
        }

        // tile finished -> epilogue (overlaps next tile's in-flight cp.async)
        if ((gc & (KITERS - 1)) == KITERS - 1) {
            int m0, n0;
            tile_coords(bx + (gc >> 6) * grid, m0, n0);
#pragma unroll
            for (int ms = 0; ms < 4; ms++) {
                const int rg = m0 + wm * 64 + ms * 16 + lr;
                float* o0 = out + (size_t)rg * NDIM;
                float* o1 = out + (size_t)(rg + 8) * NDIM;
#pragma unroll
                for (int ns = 0; ns < 8; ns++) {
                    const int cg = n0 + wn * 64 + ns * 8 + 2 * lc;
                    const float2 bv = *reinterpret_cast<const float2*>(bias + cg);
                    float2 v0, v1;
                    v0.x = acc[ms][ns][0] + bv.x;  v0.y = acc[ms][ns][1] + bv.y;
                    v1.x = acc[ms][ns][2] + bv.x;  v1.y = acc[ms][ns][3] + bv.y;
                    *reinterpret_cast<float2*>(o0 + cg) = v0;
                    *reinterpret_cast<float2*>(o1 + cg) = v1;
                    acc[ms][ns][0] = 0.f; acc[ms][ns][1] = 0.f;
                    acc[ms][ns][2] = 0.f; acc[ms][ns][3] = 0.f;
                }
            }
        }
    }
}

// ---------------------------------------------------------------------------
extern "C" void kernel_launch(void* const* d_in, const int* in_sizes, int n_in,
                              void* d_out, int out_size) {
    const float* x = (const float*)d_in[0];      // [4,2048,4096]
    const float* w = (const float*)d_in[1];      // [4096,4096]
    const float* bias = (const float*)d_in[2];   // [4096]
    const float* kk = (const float*)d_in[3];
    const float* aa = (const float*)d_in[4];
    float* out = (float*)d_out;                  // [4,2048,4096]

    prep_all<<<W_PREP_BLOCKS + X_PREP_BLOCKS, 256>>>((const float4*)w,
                                                     (const float4*)x, kk, aa);

    int sm_count = 148;
    cudaDeviceGetAttribute(&sm_count, cudaDevAttrMultiProcessorCount, 0);
    int grid = 2 * sm_count;
    if (grid > NTILES) grid = NTILES;

    cudaFuncSetAttribute(gemm_kernel, cudaFuncAttributeMaxDynamicSharedMemorySize, SMEM_BYTES);
    gemm_kernel<<<grid, 128, SMEM_BYTES>>>(bias, out);
}

// round 11
// speedup vs baseline: 1.1014x; 1.1014x over previous
#include <cuda_runtime.h>
#include <cuda_fp16.h>
#include <cstdint>
#include <math.h>

// ============================================================================
// BinaryLinear: y[8192,4096] = x[8192,4096] @ (aa*tanh(kk*W))^T + bias
// fp16 mma.sync.m16n8k16 register GEMM (fp32 acc), ldmatrix.x4, frag dbl-buffer.
// CTA 128x128, 4 warps (2x2), warp tile 64x64, 3-stage cp.async, TK=64 halves.
// 2 CTAs/SM; SW128 swizzle. Stage bases rotated (no modulo); gmem loads split
// across kq steps so the post-barrier head is only 8 ldmatrix.
// ============================================================================

#define MDIM 8192
#define NDIM 4096
#define KDIM 4096

#define TM 128
#define TN 128
#define TK 64                          // halves per stage-row (128B)
#define NSTAGES 3
#define KITERS (KDIM / TK)             // 64

#define A_STAGE_BYTES (TM * TK * 2)    // 16384
#define B_STAGE_BYTES (TN * TK * 2)    // 16384
#define STAGE_BYTES (A_STAGE_BYTES + B_STAGE_BYTES)     // 32768
#define SMEM_BYTES (NSTAGES * STAGE_BYTES)              // 98304

#define W_PREP_BLOCKS (NDIM * KDIM / 4096)   // 4096 (16 elems/thread)
#define X_PREP_BLOCKS (MDIM * KDIM / 4096)   // 8192

// fp16 operands (persistent scratch)
__device__ __half g_wh[NDIM * KDIM];   // fp16(aa*tanh(kk*W))
__device__ __half g_xh[MDIM * KDIM];   // fp16(x)

// ---------------------------------------------------------------------------
__device__ __forceinline__ uint32_t smem_u32(const void* p) {
    uint32_t a;
    asm("{ .reg .u64 t; cvta.to.shared.u64 t, %1; cvt.u32.u64 %0, t; }" : "=r"(a) : "l"(p));
    return a;
}

__device__ __forceinline__ void cp_async16(uint32_t smem_dst, const void* gmem_src) {
    asm volatile("cp.async.cg.shared.global [%0], [%1], 16;" :: "r"(smem_dst), "l"(gmem_src));
}
#define CP_COMMIT() asm volatile("cp.async.commit_group;" ::: "memory")
#define CP_WAIT(n)  asm volatile("cp.async.wait_group %0;" :: "n"(n) : "memory")

__device__ __forceinline__ void ldmatrix_x4(uint32_t& r0, uint32_t& r1,
                                            uint32_t& r2, uint32_t& r3, uint32_t addr) {
    asm volatile("ldmatrix.sync.aligned.m8n8.x4.shared.b16 {%0,%1,%2,%3}, [%4];"
                 : "=r"(r0), "=r"(r1), "=r"(r2), "=r"(r3) : "r"(addr));
}

__device__ __forceinline__ void mma_f16(float d[4], const uint32_t a[4],
                                        const uint32_t b[2], const float c[4]) {
    asm volatile(
        "mma.sync.aligned.m16n8k16.row.col.f32.f16.f16.f32 "
        "{%0,%1,%2,%3}, {%4,%5,%6,%7}, {%8,%9}, {%10,%11,%12,%13};"
        : "=f"(d[0]), "=f"(d[1]), "=f"(d[2]), "=f"(d[3])
        : "r"(a[0]), "r"(a[1]), "r"(a[2]), "r"(a[3]),
          "r"(b[0]), "r"(b[1]),
          "f"(c[0]), "f"(c[1]), "f"(c[2]), "f"(c[3]));
}

// ---------------------------------------------------------------------------
// Fused prep: blocks [0, W_PREP_BLOCKS) convert W (with tanh), the rest X.
// 16 floats -> 16 halves per thread (MLP=4).
// ---------------------------------------------------------------------------
__device__ __forceinline__ uint32_t pack2(float lo, float hi) {
    __half2 h = __floats2half2_rn(lo, hi);
    return *reinterpret_cast<uint32_t*>(&h);
}

__global__ void __launch_bounds__(256) prep_all(const float4* __restrict__ w,
                                                const float4* __restrict__ x,
                                                const float* __restrict__ kk,
                                                const float* __restrict__ aa) {
    if (blockIdx.x < W_PREP_BLOCKS) {
        int i = blockIdx.x * 256 + threadIdx.x;
        float k = *kk, a = *aa;
        float4 v0 = w[4 * i], v1 = w[4 * i + 1], v2 = w[4 * i + 2], v3 = w[4 * i + 3];
        uint4 o0, o1;
        o0.x = pack2(a * tanhf(k * v0.x), a * tanhf(k * v0.y));
        o0.y = pack2(a * tanhf(k * v0.z), a * tanhf(k * v0.w));
        o0.z = pack2(a * tanhf(k * v1.x), a * tanhf(k * v1.y));
        o0.w = pack2(a * tanhf(k * v1.z), a * tanhf(k * v1.w));
        o1.x = pack2(a * tanhf(k * v2.x), a * tanhf(k * v2.y));
        o1.y = pack2(a * tanhf(k * v2.z), a * tanhf(k * v2.w));
        o1.z = pack2(a * tanhf(k * v3.x), a * tanhf(k * v3.y));
        o1.w = pack2(a * tanhf(k * v3.z), a * tanhf(k * v3.w));
        reinterpret_cast<uint4*>(g_wh)[2 * i] = o0;
        reinterpret_cast<uint4*>(g_wh)[2 * i + 1] = o1;
    } else {
        int i = (blockIdx.x - W_PREP_BLOCKS) * 256 + threadIdx.x;
        float4 v0 = x[4 * i], v1 = x[4 * i + 1], v2 = x[4 * i + 2], v3 = x[4 * i + 3];
        uint4 o0, o1;
        o0.x = pack2(v0.x, v0.y);  o0.y = pack2(v0.z, v0.w);
        o0.z = pack2(v1.x, v1.y);  o0.w = pack2(v1.z, v1.w);
        o1.x = pack2(v2.x, v2.y);  o1.y = pack2(v2.z, v2.w);
        o1.z = pack2(v3.x, v3.y);  o1.w = pack2(v3.z, v3.w);
        reinterpret_cast<uint4*>(g_xh)[2 * i] = o0;
        reinterpret_cast<uint4*>(g_xh)[2 * i + 1] = o1;
    }
}

// ---------------------------------------------------------------------------
// SMEM: rows of 64 halves (128B = 8 x 16B granules), SW128 swizzle:
// granule c of row r stored at slot (c ^ (r&7)).
// A-half / B-half loaders: 8 cp.async per thread each.
// ---------------------------------------------------------------------------
__device__ __forceinline__ void load_A(const __half* __restrict__ xh,
                                       int m0, int k0, uint32_t sdst, int tid) {
#pragma unroll
    for (int i = 0; i < 8; i++) {                 // 1024 granules
        int g = tid + i * 128;
        int row = g >> 3, c = g & 7;
        cp_async16(sdst + row * 128 + ((c ^ (row & 7)) << 4),
                   xh + (size_t)(m0 + row) * KDIM + k0 + c * 8);
    }
}

__device__ __forceinline__ void load_B(const __half* __restrict__ wh,
                                       int n0, int k0, uint32_t sdst, int tid) {
#pragma unroll
    for (int i = 0; i < 8; i++) {                 // 1024 granules
        int g = tid + i * 128;
        int row = g >> 3, c = g & 7;
        cp_async16(sdst + A_STAGE_BYTES + row * 128 + ((c ^ (row & 7)) << 4),
                   wh + (size_t)(n0 + row) * KDIM + k0 + c * 8);
    }
}

// ---------------------------------------------------------------------------
// GEMM: 4 warps (2x2), warp tile 64x64 (4 x 8 of m16n8k16), frag dbl-buffer.
// ---------------------------------------------------------------------------
__global__ void __launch_bounds__(128, 2) gemm_kernel(const float* __restrict__ bias,
                                                      float* __restrict__ out) {
    extern __shared__ char smem_raw[];
    const uint32_t sbase = smem_u32(smem_raw);

    const int tid = threadIdx.x;
    const int wid = tid >> 5;
    const int lane = tid & 31;
    const int wm = wid >> 1;          // 0..1 -> 64-row slab
    const int wn = wid & 1;           // 0..1 -> 64-col slab
    const int lr = lane >> 2;         // 0..7
    const int lc = lane & 3;          // 0..3

    // ldmatrix lane decomposition
    const int i8 = lane & 7;
    const int sel = lane >> 3;
    const int a_msel = (sel & 1) << 3;
    const int a_gsel = sel >> 1;
    const int b_nsel = (sel >> 1) << 3;
    const int b_gsel = sel & 1;
    const uint32_t aRowOff = (uint32_t)(wm * 64 + a_msel + i8) * 128;
    const uint32_t bRowOff = (uint32_t)(wn * 64 + b_nsel + i8) * 128;

    // grouped tile swizzle: 64 m-tiles x 32 n-tiles, GROUP_M = 8
    const int pid = blockIdx.x;
    const int group = pid >> 8;                   // / (8*32)
    const int rem = pid & 255;
    const int pm = (group << 3) + (rem & 7);
    const int pn = rem >> 3;
    const int m0 = pm * TM;
    const int n0 = pn * TN;

    float acc[4][8][4];
#pragma unroll
    for (int i = 0; i < 4; i++)
#pragma unroll
        for (int j = 0; j < 8; j++) {
            acc[i][j][0] = 0.f; acc[i][j][1] = 0.f;
            acc[i][j][2] = 0.f; acc[i][j][3] = 0.f;
        }

    // prologue: fill stages 0,1
#pragma unroll
    for (int s = 0; s < NSTAGES - 1; s++) {
        load_A(g_xh, m0, s * TK, sbase + s * STAGE_BYTES, tid);
        load_B(g_wh, n0, s * TK, sbase + s * STAGE_BYTES, tid);
        CP_COMMIT();
    }

    uint32_t af[2][4][4];
    uint32_t bf[2][8][2];

    uint32_t curBase = sbase;                         // stage being consumed
    uint32_t ldBase = sbase + 2 * STAGE_BYTES;        // stage being loaded
    const uint32_t sEnd = sbase + NSTAGES * STAGE_BYTES;

    for (int it = 0; it < KITERS; ++it) {
        CP_WAIT(1);              // stage `it` resident (one group per iter)
        __syncthreads();

        const uint32_t aBase = curBase;
        const uint32_t bBase = curBase + A_STAGE_BYTES;

        // post-barrier head: ONLY the kq=0 frag loads (8 ldmatrix)
        {
            const int ga = a_gsel, gb = b_gsel;
#pragma unroll
            for (int ms = 0; ms < 4; ms++)
                ldmatrix_x4(af[0][ms][0], af[0][ms][1], af[0][ms][2], af[0][ms][3],
                            aBase + aRowOff + ms * 2048 + ((ga ^ i8) << 4));
#pragma unroll
            for (int nsp = 0; nsp < 4; nsp++)
                ldmatrix_x4(bf[0][2 * nsp][0], bf[0][2 * nsp][1],
                            bf[0][2 * nsp + 1][0], bf[0][2 * nsp + 1][1],
                            bBase + bRowOff + nsp * 2048 + ((gb ^ i8) << 4));
        }

        const int jt = it + NSTAGES - 1;          // stage to load this iter
        const int k0 = jt * TK;
        const bool doLoad = (jt < KITERS);

#pragma unroll
        for (int kq = 0; kq < 4; kq++) {          // 4 x k16 steps
            const int cur = kq & 1, nxt = cur ^ 1;
            if (kq < 3) {                         // prefetch kq+1 frags
                const int ga = 2 * (kq + 1) + a_gsel;
                const int gb = 2 * (kq + 1) + b_gsel;
#pragma unroll
                for (int ms = 0; ms < 4; ms++)
                    ldmatrix_x4(af[nxt][ms][0], af[nxt][ms][1],
                                af[nxt][ms][2], af[nxt][ms][3],
                                aBase + aRowOff + ms * 2048 + ((ga ^ i8) << 4));
#pragma unroll
                for (int nsp = 0; nsp < 4; nsp++)
                    ldmatrix_x4(bf[nxt][2 * nsp][0], bf[nxt][2 * nsp][1],
                                bf[nxt][2 * nsp + 1][0], bf[nxt][2 * nsp + 1][1],
                                bBase + bRowOff + nsp * 2048 + ((gb ^ i8) << 4));
            }
#pragma unroll
            for (int ms = 0; ms < 4; ms++)
#pragma unroll
                for (int ns = 0; ns < 8; ns++)
                    mma_f16(acc[ms][ns], af[cur][ms], bf[cur][ns], acc[ms][ns]);

            // gmem loads for stage it+2, issued under MMA shadow
            if (kq == 0 && doLoad) load_A(g_xh, m0, k0, ldBase, tid);
            if (kq == 1 && doLoad) load_B(g_wh, n0, k0, ldBase, tid);
        }
        CP_COMMIT();             // always one group per iter: CP_WAIT(1) valid

        // rotate stage bases (no modulo)
        curBase += STAGE_BYTES;  if (curBase == sEnd) curBase = sbase;
        ldBase  += STAGE_BYTES;  if (ldBase  == sEnd) ldBase  = sbase;
    }

    // epilogue: c0,c1 at (row, 2*lc), c2,c3 at (row+8, 2*lc)
#pragma unroll
    for (int ms = 0; ms < 4; ms++) {
        const int rg = m0 + wm * 64 + ms * 16 + lr;
        float* o0 = out + (size_t)rg * NDIM;
        float* o1 = out + (size_t)(rg + 8) * NDIM;
#pragma unroll
        for (int ns = 0; ns < 8; ns++) {
            const int cg = n0 + wn * 64 + ns * 8 + 2 * lc;
            const float2 bv = *reinterpret_cast<const float2*>(bias + cg);
            float2 v0, v1;
            v0.x = acc[ms][ns][0] + bv.x;  v0.y = acc[ms][ns][1] + bv.y;
            v1.x = acc[ms][ns][2] + bv.x;  v1.y = acc[ms][ns][3] + bv.y;
            *reinterpret_cast<float2*>(o0 + cg) = v0;
            *reinterpret_cast<float2*>(o1 + cg) = v1;
        }
    }
}

// ---------------------------------------------------------------------------
extern "C" void kernel_launch(void* const* d_in, const int* in_sizes, int n_in,
                              void* d_out, int out_size) {
    const float* x = (const float*)d_in[0];      // [4,2048,4096]
    const float* w = (const float*)d_in[1];      // [4096,4096]
    const float* bias = (const float*)d_in[2];   // [4096]
    const float* kk = (const float*)d_in[3];
    const float* aa = (const float*)d_in[4];
    float* out = (float*)d_out;                  // [4,2048,4096]

    prep_all<<<W_PREP_BLOCKS + X_PREP_BLOCKS, 256>>>((const float4*)w,
                                                     (const float4*)x, kk, aa);

    cudaFuncSetAttribute(gemm_kernel, cudaFuncAttributeMaxDynamicSharedMemorySize, SMEM_BYTES);
    gemm_kernel<<<(MDIM / TM) * (NDIM / TN), 128, SMEM_BYTES>>>(bias, out);
}

// round 12
// speedup vs baseline: 1.1344x; 1.0299x over previous
#include <cuda_runtime.h>
#include <cuda_fp16.h>
#include <cstdint>
#include <math.h>

// ============================================================================
// BinaryLinear: y[8192,4096] = x[8192,4096] @ (aa*tanh(kk*W))^T + bias
// fp16 mma.sync.m16n8k16 register GEMM (fp32 acc), ldmatrix.x4, frag dbl-buffer.
// CTA 128x128, 4 warps (2x2), warp tile 64x64, 3-stage cp.async, TK=64 halves.
// 2 CTAs/SM; SW128 swizzle. R9 structure (front-batched gmem burst) with
// stage-pointer rotation instead of modulo.
// ============================================================================

#define MDIM 8192
#define NDIM 4096
#define KDIM 4096

#define TM 128
#define TN 128
#define TK 64                          // halves per stage-row (128B)
#define NSTAGES 3
#define KITERS (KDIM / TK)             // 64

#define A_STAGE_BYTES (TM * TK * 2)    // 16384
#define B_STAGE_BYTES (TN * TK * 2)    // 16384
#define STAGE_BYTES (A_STAGE_BYTES + B_STAGE_BYTES)     // 32768
#define SMEM_BYTES (NSTAGES * STAGE_BYTES)              // 98304

#define W_PREP_BLOCKS (NDIM * KDIM / 4096)   // 4096 (16 elems/thread)
#define X_PREP_BLOCKS (MDIM * KDIM / 4096)   // 8192

// fp16 operands (persistent scratch)
__device__ __half g_wh[NDIM * KDIM];   // fp16(aa*tanh(kk*W))
__device__ __half g_xh[MDIM * KDIM];   // fp16(x)

// ---------------------------------------------------------------------------
__device__ __forceinline__ uint32_t smem_u32(const void* p) {
    uint32_t a;
    asm("{ .reg .u64 t; cvta.to.shared.u64 t, %1; cvt.u32.u64 %0, t; }" : "=r"(a) : "l"(p));
    return a;
}

__device__ __forceinline__ void cp_async16(uint32_t smem_dst, const void* gmem_src) {
    asm volatile("cp.async.cg.shared.global [%0], [%1], 16;" :: "r"(smem_dst), "l"(gmem_src));
}
#define CP_COMMIT() asm volatile("cp.async.commit_group;" ::: "memory")
#define CP_WAIT(n)  asm volatile("cp.async.wait_group %0;" :: "n"(n) : "memory")

__device__ __forceinline__ void ldmatrix_x4(uint32_t& r0, uint32_t& r1,
                                            uint32_t& r2, uint32_t& r3, uint32_t addr) {
    asm volatile("ldmatrix.sync.aligned.m8n8.x4.shared.b16 {%0,%1,%2,%3}, [%4];"
                 : "=r"(r0), "=r"(r1), "=r"(r2), "=r"(r3) : "r"(addr));
}

__device__ __forceinline__ void mma_f16(float d[4], const uint32_t a[4],
                                        const uint32_t b[2], const float c[4]) {
    asm volatile(
        "mma.sync.aligned.m16n8k16.row.col.f32.f16.f16.f32 "
        "{%0,%1,%2,%3}, {%4,%5,%6,%7}, {%8,%9}, {%10,%11,%12,%13};"
        : "=f"(d[0]), "=f"(d[1]), "=f"(d[2]), "=f"(d[3])
        : "r"(a[0]), "r"(a[1]), "r"(a[2]), "r"(a[3]),
          "r"(b[0]), "r"(b[1]),
          "f"(c[0]), "f"(c[1]), "f"(c[2]), "f"(c[3]));
}

// ---------------------------------------------------------------------------
// Fused prep: blocks [0, W_PREP_BLOCKS) convert W (with tanh), the rest X.
// 16 floats -> 16 halves per thread (MLP=4).
// ---------------------------------------------------------------------------
__device__ __forceinline__ uint32_t pack2(float lo, float hi) {
    __half2 h = __floats2half2_rn(lo, hi);
    return *reinterpret_cast<uint32_t*>(&h);
}

__global__ void __launch_bounds__(256) prep_all(const float4* __restrict__ w,
                                                const float4* __restrict__ x,
                                                const float* __restrict__ kk,
                                                const float* __restrict__ aa) {
    if (blockIdx.x < W_PREP_BLOCKS) {
        int i = blockIdx.x * 256 + threadIdx.x;
        float k = *kk, a = *aa;
        float4 v0 = w[4 * i], v1 = w[4 * i + 1], v2 = w[4 * i + 2], v3 = w[4 * i + 3];
        uint4 o0, o1;
        o0.x = pack2(a * tanhf(k * v0.x), a * tanhf(k * v0.y));
        o0.y = pack2(a * tanhf(k * v0.z), a * tanhf(k * v0.w));
        o0.z = pack2(a * tanhf(k * v1.x), a * tanhf(k * v1.y));
        o0.w = pack2(a * tanhf(k * v1.z), a * tanhf(k * v1.w));
        o1.x = pack2(a * tanhf(k * v2.x), a * tanhf(k * v2.y));
        o1.y = pack2(a * tanhf(k * v2.z), a * tanhf(k * v2.w));
        o1.z = pack2(a * tanhf(k * v3.x), a * tanhf(k * v3.y));
        o1.w = pack2(a * tanhf(k * v3.z), a * tanhf(k * v3.w));
        reinterpret_cast<uint4*>(g_wh)[2 * i] = o0;
        reinterpret_cast<uint4*>(g_wh)[2 * i + 1] = o1;
    } else {
        int i = (blockIdx.x - W_PREP_BLOCKS) * 256 + threadIdx.x;
        float4 v0 = x[4 * i], v1 = x[4 * i + 1], v2 = x[4 * i + 2], v3 = x[4 * i + 3];
        uint4 o0, o1;
        o0.x = pack2(v0.x, v0.y);  o0.y = pack2(v0.z, v0.w);
        o0.z = pack2(v1.x, v1.y);  o0.w = pack2(v1.z, v1.w);
        o1.x = pack2(v2.x, v2.y);  o1.y = pack2(v2.z, v2.w);
        o1.z = pack2(v3.x, v3.y);  o1.w = pack2(v3.z, v3.w);
        reinterpret_cast<uint4*>(g_xh)[2 * i] = o0;
        reinterpret_cast<uint4*>(g_xh)[2 * i + 1] = o1;
    }
}

// ---------------------------------------------------------------------------
// SMEM: rows of 64 halves (128B = 8 x 16B granules), SW128 swizzle:
// granule c of row r stored at slot (c ^ (r&7)).
// Load one 64-K stage: A 128x64h + B 128x64h. 2048 granules / 128 thr = 16 ea.
// ---------------------------------------------------------------------------
__device__ __forceinline__ void load_stage(const __half* __restrict__ xh,
                                           const __half* __restrict__ wh,
                                           int m0, int n0, int k0,
                                           uint32_t sdst, int tid) {
#pragma unroll
    for (int i = 0; i < 8; i++) {                 // A: 1024 granules
        int g = tid + i * 128;
        int row = g >> 3, c = g & 7;
        cp_async16(sdst + row * 128 + ((c ^ (row & 7)) << 4),
                   xh + (size_t)(m0 + row) * KDIM + k0 + c * 8);
    }
#pragma unroll
    for (int i = 0; i < 8; i++) {                 // B: 1024 granules
        int g = tid + i * 128;
        int row = g >> 3, c = g & 7;
        cp_async16(sdst + A_STAGE_BYTES + row * 128 + ((c ^ (row & 7)) << 4),
                   wh + (size_t)(n0 + row) * KDIM + k0 + c * 8);
    }
}

// ---------------------------------------------------------------------------
// GEMM: 4 warps (2x2), warp tile 64x64 (4 x 8 of m16n8k16), frag dbl-buffer.
// ---------------------------------------------------------------------------
__global__ void __launch_bounds__(128, 2) gemm_kernel(const float* __restrict__ bias,
                                                      float* __restrict__ out) {
    extern __shared__ char smem_raw[];
    const uint32_t sbase = smem_u32(smem_raw);

    const int tid = threadIdx.x;
    const int wid = tid >> 5;
    const int lane = tid & 31;
    const int wm = wid >> 1;          // 0..1 -> 64-row slab
    const int wn = wid & 1;           // 0..1 -> 64-col slab
    const int lr = lane >> 2;         // 0..7
    const int lc = lane & 3;          // 0..3

    // ldmatrix lane decomposition
    const int i8 = lane & 7;
    const int sel = lane >> 3;
    const int a_msel = (sel & 1) << 3;
    const int a_gsel = sel >> 1;
    const int b_nsel = (sel >> 1) << 3;
    const int b_gsel = sel & 1;
    const uint32_t aRowOff = (uint32_t)(wm * 64 + a_msel + i8) * 128;
    const uint32_t bRowOff = (uint32_t)(wn * 64 + b_nsel + i8) * 128;

    // grouped tile swizzle: 64 m-tiles x 32 n-tiles, GROUP_M = 8
    const int pid = blockIdx.x;
    const int group = pid >> 8;                   // / (8*32)
    const int rem = pid & 255;
    const int pm = (group << 3) + (rem & 7);
    const int pn = rem >> 3;
    const int m0 = pm * TM;
    const int n0 = pn * TN;

    float acc[4][8][4];
#pragma unroll
    for (int i = 0; i < 4; i++)
#pragma unroll
        for (int j = 0; j < 8; j++) {
            acc[i][j][0] = 0.f; acc[i][j][1] = 0.f;
            acc[i][j][2] = 0.f; acc[i][j][3] = 0.f;
        }

    // prologue: fill stages 0,1
#pragma unroll
    for (int s = 0; s < NSTAGES - 1; s++) {
        load_stage(g_xh, g_wh, m0, n0, s * TK, sbase + s * STAGE_BYTES, tid);
        CP_COMMIT();
    }

    uint32_t af[2][4][4];
    uint32_t bf[2][8][2];

    uint32_t curBase = sbase;                         // stage being consumed
    uint32_t ldBase = sbase + 2 * STAGE_BYTES;        // stage being loaded
    const uint32_t sEnd = sbase + NSTAGES * STAGE_BYTES;

    for (int it = 0; it < KITERS; ++it) {
        CP_WAIT(1);              // stage `it` resident (one group per iter)
        __syncthreads();

        const uint32_t aBase = curBase;
        const uint32_t bBase = curBase + A_STAGE_BYTES;

        // frag load for kq=0 into buffer 0 (starts immediately post-barrier)
        {
            const int ga = a_gsel, gb = b_gsel;
#pragma unroll
            for (int ms = 0; ms < 4; ms++)
                ldmatrix_x4(af[0][ms][0], af[0][ms][1], af[0][ms][2], af[0][ms][3],
                            aBase + aRowOff + ms * 2048 + ((ga ^ i8) << 4));
#pragma unroll
            for (int nsp = 0; nsp < 4; nsp++)
                ldmatrix_x4(bf[0][2 * nsp][0], bf[0][2 * nsp][1],
                            bf[0][2 * nsp + 1][0], bf[0][2 * nsp + 1][1],
                            bBase + bRowOff + nsp * 2048 + ((gb ^ i8) << 4));
        }

        // front-batched gmem burst for stage it+2 (R9 ordering)
        const int jt = it + NSTAGES - 1;
        if (jt < KITERS)
            load_stage(g_xh, g_wh, m0, n0, jt * TK, ldBase, tid);
        CP_COMMIT();             // always commit: CP_WAIT(1) stays valid

#pragma unroll
        for (int kq = 0; kq < 4; kq++) {          // 4 x k16 steps
            const int cur = kq & 1, nxt = cur ^ 1;
            if (kq < 3) {                         // prefetch kq+1 frags
                const int ga = 2 * (kq + 1) + a_gsel;
                const int gb = 2 * (kq + 1) + b_gsel;
#pragma unroll
                for (int ms = 0; ms < 4; ms++)
                    ldmatrix_x4(af[nxt][ms][0], af[nxt][ms][1],
                                af[nxt][ms][2], af[nxt][ms][3],
                                aBase + aRowOff + ms * 2048 + ((ga ^ i8) << 4));
#pragma unroll
                for (int nsp = 0; nsp < 4; nsp++)
                    ldmatrix_x4(bf[nxt][2 * nsp][0], bf[nxt][2 * nsp][1],
                                bf[nxt][2 * nsp + 1][0], bf[nxt][2 * nsp + 1][1],
                                bBase + bRowOff + nsp * 2048 + ((gb ^ i8) << 4));
            }
#pragma unroll
            for (int ms = 0; ms < 4; ms++)
#pragma unroll
                for (int ns = 0; ns < 8; ns++)
                    mma_f16(acc[ms][ns], af[cur][ms], bf[cur][ns], acc[ms][ns]);
        }

        // rotate stage bases (no modulo)
        curBase += STAGE_BYTES;  if (curBase == sEnd) curBase = sbase;
        ldBase  += STAGE_BYTES;  if (ldBase  == sEnd) ldBase  = sbase;
    }

    // epilogue: c0,c1 at (row, 2*lc), c2,c3 at (row+8, 2*lc)
#pragma unroll
    for (int ms = 0; ms < 4; ms++) {
        const int rg = m0 + wm * 64 + ms * 16 + lr;
        float* o0 = out + (size_t)rg * NDIM;
        float* o1 = out + (size_t)(rg + 8) * NDIM;
#pragma unroll
        for (int ns = 0; ns < 8; ns++) {
            const int cg = n0 + wn * 64 + ns * 8 + 2 * lc;
            const float2 bv = *reinterpret_cast<const float2*>(bias + cg);
            float2 v0, v1;
            v0.x = acc[ms][ns][0] + bv.x;  v0.y = acc[ms][ns][1] + bv.y;
            v1.x = acc[ms][ns][2] + bv.x;  v1.y = acc[ms][ns][3] + bv.y;
            *reinterpret_cast<float2*>(o0 + cg) = v0;
            *reinterpret_cast<float2*>(o1 + cg) = v1;
        }
    }
}

// ---------------------------------------------------------------------------
extern "C" void kernel_launch(void* const* d_in, const int* in_sizes, int n_in,
                              void* d_out, int out_size) {
    const float* x = (const float*)d_in[0];      // [4,2048,4096]
    const float* w = (const float*)d_in[1];      // [4096,4096]
    const float* bias = (const float*)d_in[2];   // [4096]
    const float* kk = (const float*)d_in[3];
    const float* aa = (const float*)d_in[4];
    float* out = (float*)d_out;                  // [4,2048,4096]

    prep_all<<<W_PREP_BLOCKS + X_PREP_BLOCKS, 256>>>((const float4*)w,
                                                     (const float4*)x, kk, aa);

    cudaFuncSetAttribute(gemm_kernel, cudaFuncAttributeMaxDynamicSharedMemorySize, SMEM_BYTES);
    gemm_kernel<<<(MDIM / TM) * (NDIM / TN), 128, SMEM_BYTES>>>(bias, out);
}